// round 1
// baseline (speedup 1.0000x reference)
#include <cuda_runtime.h>
#include <math.h>

#define NN 50000
#define EE 640000
#define F  128

// Scratch (static device globals: no allocation anywhere)
__device__ float g_h[NN * F];      // h = x @ W  (also mapped_fea)
__device__ float g_hp[NN * F];     // h_prime accumulator
__device__ float g_rowsum[NN];     // segment_sum of e over src
__device__ float g_s1[NN];         // h[i] . a1
__device__ float g_s2[NN];         // h[i] . a2
__device__ float g_e[EE];          // per-edge exp(-leaky_relu(score))

// ---------------------------------------------------------------- init
__global__ void k_init() {
    int i = blockIdx.x * blockDim.x + threadIdx.x;
    if (i < NN * F) g_hp[i] = 0.0f;
    if (i < NN)     g_rowsum[i] = 0.0f;
}

// ------------------------------------------------- GEMM + s1/s2 epilogue
// Block: 256 threads, computes a 64(M) x 128(N) tile, K tiled by 32.
// Thread (ty = tid/32, tx = tid%32) owns 8 rows x 4 cols.
__global__ void k_gemm(const float* __restrict__ x,
                       const float* __restrict__ W,
                       const float* __restrict__ a) {
    __shared__ float xs[64][32];
    __shared__ float ws[32][128];

    const int tid = threadIdx.x;
    const int tx = tid & 31;
    const int ty = tid >> 5;
    const int rowBase = blockIdx.x * 64;

    float acc[8][4];
#pragma unroll
    for (int i = 0; i < 8; i++)
#pragma unroll
        for (int j = 0; j < 4; j++) acc[i][j] = 0.0f;

    for (int k0 = 0; k0 < F; k0 += 32) {
        // load x tile (64 rows x 32 k), coalesced: warp covers one row's 128B
#pragma unroll
        for (int idx = tid; idx < 64 * 32; idx += 256) {
            int r = idx >> 5, k = idx & 31;
            int row = rowBase + r;
            xs[r][k] = (row < NN) ? x[row * F + k0 + k] : 0.0f;
        }
        // load W chunk (32 k x 128 cols), coalesced
#pragma unroll
        for (int idx = tid; idx < 32 * 128; idx += 256) {
            int k = idx >> 7, c = idx & 127;
            ws[k][c] = W[(k0 + k) * F + c];
        }
        __syncthreads();

#pragma unroll
        for (int kk = 0; kk < 32; kk++) {
            float4 w4 = *(const float4*)&ws[kk][tx * 4];   // LDS.128, conflict-free
#pragma unroll
            for (int i = 0; i < 8; i++) {
                float xv = xs[ty * 8 + i][kk];             // broadcast
                acc[i][0] += xv * w4.x;
                acc[i][1] += xv * w4.y;
                acc[i][2] += xv * w4.z;
                acc[i][3] += xv * w4.w;
            }
        }
        __syncthreads();
    }

    // epilogue: write h, and fused s1/s2 = h.a1, h.a2 via warp reduction
    float a1v[4], a2v[4];
#pragma unroll
    for (int j = 0; j < 4; j++) {
        a1v[j] = a[tx * 4 + j];
        a2v[j] = a[F + tx * 4 + j];
    }

#pragma unroll
    for (int i = 0; i < 8; i++) {
        int row = rowBase + ty * 8 + i;
        float p1 = acc[i][0] * a1v[0] + acc[i][1] * a1v[1] +
                   acc[i][2] * a1v[2] + acc[i][3] * a1v[3];
        float p2 = acc[i][0] * a2v[0] + acc[i][1] * a2v[1] +
                   acc[i][2] * a2v[2] + acc[i][3] * a2v[3];
#pragma unroll
        for (int off = 16; off > 0; off >>= 1) {
            p1 += __shfl_xor_sync(0xffffffffu, p1, off);
            p2 += __shfl_xor_sync(0xffffffffu, p2, off);
        }
        if (row < NN) {
            float4 o;
            o.x = acc[i][0]; o.y = acc[i][1]; o.z = acc[i][2]; o.w = acc[i][3];
            *(float4*)&g_h[row * F + tx * 4] = o;
            if (tx == 0) {
                g_s1[row] = p1;
                g_s2[row] = p2;
            }
        }
    }
}

// ---------------------------------------------------------------- edges
__global__ void k_edge(const int* __restrict__ src, const int* __restrict__ dst) {
    int e = blockIdx.x * blockDim.x + threadIdx.x;
    if (e >= EE) return;
    int s = src[e], d = dst[e];
    float sc = g_s1[s] + g_s2[d];
    float lr = (sc >= 0.0f) ? sc : 0.2f * sc;   // leaky_relu(sc, 0.2)
    float ev = expf(-lr);
    g_e[e] = ev;
    atomicAdd(&g_rowsum[s], ev);
}

// --------------------------------------------------------------- scatter
// One warp per edge: h_prime[src] += e * h[dst]   (4 floats per lane)
__global__ void k_scatter(const int* __restrict__ src, const int* __restrict__ dst) {
    int t = blockIdx.x * blockDim.x + threadIdx.x;
    int e = t >> 5;
    if (e >= EE) return;
    int lane = t & 31;
    int s = src[e], d = dst[e];
    float ev = g_e[e];
    float4 v = *(const float4*)(g_h + (size_t)d * F + lane * 4);
    float* o = g_hp + (size_t)s * F + lane * 4;
    atomicAdd(o + 0, ev * v.x);
    atomicAdd(o + 1, ev * v.y);
    atomicAdd(o + 2, ev * v.z);
    atomicAdd(o + 3, ev * v.w);
}

// --------------------------------------------------------------- finalize
__global__ void k_final(float* __restrict__ out) {
    int t = blockIdx.x * blockDim.x + threadIdx.x;   // over NN*32 float4s
    if (t >= NN * 32) return;
    int node = t >> 5;
    float inv = 1.0f / (g_rowsum[node] + 1e-16f);
    float4 h4 = *(const float4*)(g_h + (size_t)t * 4);
    float4 p4 = *(const float4*)(g_hp + (size_t)t * 4);
    float4 r;
    float v;
    v = h4.x - p4.x * inv; r.x = (v > 0.0f) ? v : expm1f(v);
    v = h4.y - p4.y * inv; r.y = (v > 0.0f) ? v : expm1f(v);
    v = h4.z - p4.z * inv; r.z = (v > 0.0f) ? v : expm1f(v);
    v = h4.w - p4.w * inv; r.w = (v > 0.0f) ? v : expm1f(v);
    *(float4*)(out + (size_t)t * 4) = r;
}

// ---------------------------------------------------------------- launch
extern "C" void kernel_launch(void* const* d_in, const int* in_sizes, int n_in,
                              void* d_out, int out_size) {
    const float* x = (const float*)d_in[0];
    const float* W = (const float*)d_in[1];
    const float* a = (const float*)d_in[2];
    const int*   ei = (const int*)d_in[3];
    const int* src = ei;          // edge_index row 0
    const int* dst = ei + EE;     // edge_index row 1
    float* out = (float*)d_out;

    k_init   <<<(NN * F + 255) / 256, 256>>>();
    k_gemm   <<<(NN + 63) / 64,       256>>>(x, W, a);
    k_edge   <<<(EE + 255) / 256,     256>>>(src, dst);
    k_scatter<<<((size_t)EE * 32 + 255) / 256, 256>>>(src, dst);
    k_final  <<<(NN * 32 + 255) / 256, 256>>>(out);
}

// round 4
// speedup vs baseline: 1.9588x; 1.9588x over previous
#include <cuda_runtime.h>
#include <math.h>

#define NN 50000
#define EE 640000
#define F  128
#define NB ((NN + 1023) / 1024)   // 49 scan blocks

// Scratch (static device globals: no allocation anywhere)
__device__ float g_h[NN * F];      // h = x @ W  (also mapped_fea)
__device__ float g_s1[NN];         // h[i] . a1
__device__ float g_s2[NN];         // h[i] . a2
__device__ int   g_count[NN];      // per-src edge count
__device__ int   g_rowstart[NN];   // exclusive prefix of count
__device__ int   g_cur[NN];        // permute cursors
__device__ int   g_blocksum[64];   // scan block sums
__device__ int   g_edst[EE];       // dst indices sorted by src

// ---------------------------------------------------------------- init
__global__ void k_init() {
    int i = blockIdx.x * blockDim.x + threadIdx.x;
    if (i < NN) { g_count[i] = 0; g_cur[i] = 0; }
}

// ------------------------------------------------- GEMM + s1/s2 epilogue
__global__ void k_gemm(const float* __restrict__ x,
                       const float* __restrict__ W,
                       const float* __restrict__ a) {
    __shared__ float xs[64][32];
    __shared__ float ws[32][128];

    const int tid = threadIdx.x;
    const int tx = tid & 31;
    const int ty = tid >> 5;
    const int rowBase = blockIdx.x * 64;

    float acc[8][4];
#pragma unroll
    for (int i = 0; i < 8; i++)
#pragma unroll
        for (int j = 0; j < 4; j++) acc[i][j] = 0.0f;

    for (int k0 = 0; k0 < F; k0 += 32) {
#pragma unroll
        for (int idx = tid; idx < 64 * 32; idx += 256) {
            int r = idx >> 5, k = idx & 31;
            int row = rowBase + r;
            xs[r][k] = (row < NN) ? x[row * F + k0 + k] : 0.0f;
        }
#pragma unroll
        for (int idx = tid; idx < 32 * 128; idx += 256) {
            int k = idx >> 7, c = idx & 127;
            ws[k][c] = W[(k0 + k) * F + c];
        }
        __syncthreads();

#pragma unroll
        for (int kk = 0; kk < 32; kk++) {
            float4 w4 = *(const float4*)&ws[kk][tx * 4];
#pragma unroll
            for (int i = 0; i < 8; i++) {
                float xv = xs[ty * 8 + i][kk];
                acc[i][0] += xv * w4.x;
                acc[i][1] += xv * w4.y;
                acc[i][2] += xv * w4.z;
                acc[i][3] += xv * w4.w;
            }
        }
        __syncthreads();
    }

    float a1v[4], a2v[4];
#pragma unroll
    for (int j = 0; j < 4; j++) {
        a1v[j] = a[tx * 4 + j];
        a2v[j] = a[F + tx * 4 + j];
    }

#pragma unroll
    for (int i = 0; i < 8; i++) {
        int row = rowBase + ty * 8 + i;
        float p1 = acc[i][0] * a1v[0] + acc[i][1] * a1v[1] +
                   acc[i][2] * a1v[2] + acc[i][3] * a1v[3];
        float p2 = acc[i][0] * a2v[0] + acc[i][1] * a2v[1] +
                   acc[i][2] * a2v[2] + acc[i][3] * a2v[3];
#pragma unroll
        for (int off = 16; off > 0; off >>= 1) {
            p1 += __shfl_xor_sync(0xffffffffu, p1, off);
            p2 += __shfl_xor_sync(0xffffffffu, p2, off);
        }
        if (row < NN) {
            float4 o;
            o.x = acc[i][0]; o.y = acc[i][1]; o.z = acc[i][2]; o.w = acc[i][3];
            *(float4*)&g_h[row * F + tx * 4] = o;
            if (tx == 0) { g_s1[row] = p1; g_s2[row] = p2; }
        }
    }
}

// -------------------------------------------------------- CSR build
__global__ void k_hist(const int* __restrict__ src) {
    int e = blockIdx.x * blockDim.x + threadIdx.x;
    if (e < EE) atomicAdd(&g_count[src[e]], 1);
}

// per-block inclusive scan over 1024 counts -> exclusive rowstart + blocksum
__global__ void k_scan1() {
    __shared__ int warpsums[32];
    int i = blockIdx.x * 1024 + threadIdx.x;
    int lane = threadIdx.x & 31, w = threadIdx.x >> 5;
    int v = (i < NN) ? g_count[i] : 0;
    int sc = v;
#pragma unroll
    for (int off = 1; off < 32; off <<= 1) {
        int n = __shfl_up_sync(0xffffffffu, sc, off);
        if (lane >= off) sc += n;
    }
    if (lane == 31) warpsums[w] = sc;
    __syncthreads();
    if (w == 0) {
        int ws = warpsums[lane];
#pragma unroll
        for (int off = 1; off < 32; off <<= 1) {
            int n = __shfl_up_sync(0xffffffffu, ws, off);
            if (lane >= off) ws += n;
        }
        warpsums[lane] = ws;
    }
    __syncthreads();
    int base = (w > 0) ? warpsums[w - 1] : 0;
    int incl = sc + base;
    if (i < NN) g_rowstart[i] = incl - v;
    if (threadIdx.x == 1023) g_blocksum[blockIdx.x] = incl;
}

// scan the 49 block sums (single block, smem Hillis-Steele)
__global__ void k_scan2() {
    __shared__ int s[64];
    int t = threadIdx.x;
    s[t] = (t < NB) ? g_blocksum[t] : 0;
    __syncthreads();
#pragma unroll
    for (int off = 1; off < 64; off <<= 1) {
        int v = (t >= off) ? s[t - off] : 0;
        __syncthreads();
        s[t] += v;
        __syncthreads();
    }
    if (t < NB) g_blocksum[t] = s[t] - ((t < NB) ? 0 : 0) - ((t == 0) ? s[0] : s[t] - s[t]); // placeholder (fixed below)
}

// exclusive variant done explicitly to avoid cleverness:
__global__ void k_scan2b() {
    __shared__ int s[64];
    int t = threadIdx.x;
    int v = (t < NB) ? g_blocksum[t] : 0;
    s[t] = v;
    __syncthreads();
#pragma unroll
    for (int off = 1; off < 64; off <<= 1) {
        int add = (t >= off) ? s[t - off] : 0;
        __syncthreads();
        s[t] += add;
        __syncthreads();
    }
    if (t < NB) g_blocksum[t] = s[t] - v;   // exclusive
}

__global__ void k_scan3() {
    int i = blockIdx.x * 1024 + threadIdx.x;
    if (i < NN) g_rowstart[i] += g_blocksum[blockIdx.x];
}

__global__ void k_permute(const int* __restrict__ src, const int* __restrict__ dst) {
    int e = blockIdx.x * blockDim.x + threadIdx.x;
    if (e >= EE) return;
    int s = src[e];
    int pos = g_rowstart[s] + atomicAdd(&g_cur[s], 1);
    g_edst[pos] = dst[e];
}

// ------------------------------------------- gather + finalize (fused)
// One warp per node; no atomics.
__global__ void k_gather(float* __restrict__ out) {
    int warp = blockIdx.x * 8 + (threadIdx.x >> 5);
    if (warp >= NN) return;
    int lane = threadIdx.x & 31;
    int start = g_rowstart[warp];
    int len = g_count[warp];
    float s1v = g_s1[warp];

    float4 acc = make_float4(0.f, 0.f, 0.f, 0.f);
    float rowsum = 0.0f;

    int j = 0;
    for (; j + 1 < len; j += 2) {
        int d0 = g_edst[start + j];
        int d1 = g_edst[start + j + 1];
        float sc0 = s1v + g_s2[d0];
        float sc1 = s1v + g_s2[d1];
        float lr0 = (sc0 >= 0.f) ? sc0 : 0.2f * sc0;
        float lr1 = (sc1 >= 0.f) ? sc1 : 0.2f * sc1;
        float ev0 = expf(-lr0);
        float ev1 = expf(-lr1);
        float4 v0 = *(const float4*)(g_h + (size_t)d0 * F + lane * 4);
        float4 v1 = *(const float4*)(g_h + (size_t)d1 * F + lane * 4);
        rowsum += ev0 + ev1;
        acc.x += ev0 * v0.x + ev1 * v1.x;
        acc.y += ev0 * v0.y + ev1 * v1.y;
        acc.z += ev0 * v0.z + ev1 * v1.z;
        acc.w += ev0 * v0.w + ev1 * v1.w;
    }
    if (j < len) {
        int d0 = g_edst[start + j];
        float sc0 = s1v + g_s2[d0];
        float lr0 = (sc0 >= 0.f) ? sc0 : 0.2f * sc0;
        float ev0 = expf(-lr0);
        float4 v0 = *(const float4*)(g_h + (size_t)d0 * F + lane * 4);
        rowsum += ev0;
        acc.x += ev0 * v0.x; acc.y += ev0 * v0.y;
        acc.z += ev0 * v0.z; acc.w += ev0 * v0.w;
    }

    float inv = 1.0f / (rowsum + 1e-16f);
    float4 h4 = *(const float4*)(g_h + (size_t)warp * F + lane * 4);
    float4 r;
    float v;
    v = h4.x - acc.x * inv; r.x = (v > 0.f) ? v : expm1f(v);
    v = h4.y - acc.y * inv; r.y = (v > 0.f) ? v : expm1f(v);
    v = h4.z - acc.z * inv; r.z = (v > 0.f) ? v : expm1f(v);
    v = h4.w - acc.w * inv; r.w = (v > 0.f) ? v : expm1f(v);
    *(float4*)(out + (size_t)warp * F + lane * 4) = r;
}

// ---------------------------------------------------------------- launch
extern "C" void kernel_launch(void* const* d_in, const int* in_sizes, int n_in,
                              void* d_out, int out_size) {
    const float* x = (const float*)d_in[0];
    const float* W = (const float*)d_in[1];
    const float* a = (const float*)d_in[2];
    const int*   ei = (const int*)d_in[3];
    const int* src = ei;          // edge_index row 0
    const int* dst = ei + EE;     // edge_index row 1
    float* out = (float*)d_out;

    k_init   <<<(NN + 255) / 256, 256>>>();
    k_gemm   <<<(NN + 63) / 64,   256>>>(x, W, a);
    k_hist   <<<(EE + 255) / 256, 256>>>(src);
    k_scan1  <<<NB, 1024>>>();
    k_scan2b <<<1, 64>>>();
    k_scan3  <<<NB, 1024>>>();
    k_permute<<<(EE + 255) / 256, 256>>>(src, dst);
    k_gather <<<(NN + 7) / 8, 256>>>(out);
}

// round 5
// speedup vs baseline: 2.7732x; 1.4157x over previous
#include <cuda_runtime.h>
#include <math.h>

#define NN 50000
#define EE 640000
#define F  128
#define NB ((NN + 1023) / 1024)   // 49 scan blocks

// Scratch (static device globals: no allocation anywhere)
__device__ float g_h[NN * F];      // h = x @ W  (also mapped_fea)
__device__ float g_s1[NN];         // h[i] . a1
__device__ float g_s2[NN];         // h[i] . a2
__device__ int   g_count[NN];      // per-src edge count
__device__ int   g_rowstart[NN];   // exclusive prefix of count
__device__ int   g_cur[NN];        // permute cursors
__device__ int   g_blocksum[64];   // scan block sums
__device__ int2  g_pair[EE];       // (dst, bitcast(e)) sorted by src

// packed f32x2 FMA: d.lo += a.lo*b.lo ; d.hi += a.hi*b.hi  (one fma-pipe slot)
#define FMA2(d, a, b) \
    asm("fma.rn.f32x2 %0, %1, %2, %0;" : "+l"(d) : "l"(a), "l"(b))

// ---------------------------------------------------------------- init
__global__ void k_init() {
    int i = blockIdx.x * blockDim.x + threadIdx.x;
    if (i < NN) { g_count[i] = 0; g_cur[i] = 0; }
}

// ------------------------------------------------- GEMM + s1/s2 epilogue
// Block: 256 threads (8 warps). Tile 64(M) x 128(N), K chunks of 32.
// Warp ty owns rows ty*8..ty*8+7 exclusively (x reads are pure broadcasts).
// Thread: 8 rows x 4 cols, accumulated as 8x2 packed f32x2.
__global__ void k_gemm(const float* __restrict__ x,
                       const float* __restrict__ W,
                       const float* __restrict__ a) {
    __shared__ __align__(16) float xs_dup[32][132];  // [k][2*row] duplicated x
    __shared__ __align__(16) float ws[32][128];

    const int tid = threadIdx.x;
    const int tx = tid & 31;         // lane
    const int ty = tid >> 5;         // warp = row group
    const int rowBase = blockIdx.x * 64;

    unsigned long long acc2[8][2];
#pragma unroll
    for (int i = 0; i < 8; i++) { acc2[i][0] = 0ULL; acc2[i][1] = 0ULL; }

    for (int k0 = 0; k0 < F; k0 += 32) {
        // x tile: 64 rows x 32 k -> dup-stored as (v,v) float2 pairs
#pragma unroll
        for (int p = 0; p < 2; p++) {
            int idx = p * 256 + tid;          // 512 float4 slots
            int r = idx >> 3;                 // 0..63
            int kg = idx & 7;                 // 0..7 (groups of 4 k)
            int row = rowBase + r;
            float4 v = make_float4(0.f, 0.f, 0.f, 0.f);
            if (row < NN) v = *(const float4*)&x[(size_t)row * F + k0 + kg * 4];
            *(float2*)&xs_dup[kg * 4 + 0][2 * r] = make_float2(v.x, v.x);
            *(float2*)&xs_dup[kg * 4 + 1][2 * r] = make_float2(v.y, v.y);
            *(float2*)&xs_dup[kg * 4 + 2][2 * r] = make_float2(v.z, v.z);
            *(float2*)&xs_dup[kg * 4 + 3][2 * r] = make_float2(v.w, v.w);
        }
        // W chunk: 32 k x 128 cols, natural layout (adjacent cols = f32x2 pair)
#pragma unroll
        for (int p = 0; p < 4; p++) {
            int idx = p * 256 + tid;          // 1024 float4 slots
            int k = idx >> 5, c4 = idx & 31;
            *(float4*)&ws[k][c4 * 4] = *(const float4*)&W[(size_t)(k0 + k) * F + c4 * 4];
        }
        __syncthreads();

#pragma unroll
        for (int kk = 0; kk < 32; kk++) {
            // w: 4 cols = 2 packed pairs, one LDS.128
            ulonglong2 wv = *(const ulonglong2*)&ws[kk][tx * 4];
#pragma unroll
            for (int i = 0; i < 8; i++) {
                // (x,x) dup pair, LDS.64 broadcast (all lanes same addr)
                unsigned long long xv =
                    *(const unsigned long long*)&xs_dup[kk][2 * (ty * 8 + i)];
                FMA2(acc2[i][0], xv, wv.x);
                FMA2(acc2[i][1], xv, wv.y);
            }
        }
        __syncthreads();
    }

    // unpack accumulators
    float acc[8][4];
#pragma unroll
    for (int i = 0; i < 8; i++) {
        acc[i][0] = __uint_as_float((unsigned)(acc2[i][0] & 0xffffffffULL));
        acc[i][1] = __uint_as_float((unsigned)(acc2[i][0] >> 32));
        acc[i][2] = __uint_as_float((unsigned)(acc2[i][1] & 0xffffffffULL));
        acc[i][3] = __uint_as_float((unsigned)(acc2[i][1] >> 32));
    }

    // epilogue: write h; fused s1/s2 = h.a1, h.a2 via warp reduction
    float a1v[4], a2v[4];
#pragma unroll
    for (int j = 0; j < 4; j++) {
        a1v[j] = a[tx * 4 + j];
        a2v[j] = a[F + tx * 4 + j];
    }

#pragma unroll
    for (int i = 0; i < 8; i++) {
        int row = rowBase + ty * 8 + i;
        float p1 = acc[i][0] * a1v[0] + acc[i][1] * a1v[1] +
                   acc[i][2] * a1v[2] + acc[i][3] * a1v[3];
        float p2 = acc[i][0] * a2v[0] + acc[i][1] * a2v[1] +
                   acc[i][2] * a2v[2] + acc[i][3] * a2v[3];
#pragma unroll
        for (int off = 16; off > 0; off >>= 1) {
            p1 += __shfl_xor_sync(0xffffffffu, p1, off);
            p2 += __shfl_xor_sync(0xffffffffu, p2, off);
        }
        if (row < NN) {
            float4 o;
            o.x = acc[i][0]; o.y = acc[i][1]; o.z = acc[i][2]; o.w = acc[i][3];
            *(float4*)&g_h[row * F + tx * 4] = o;
            if (tx == 0) { g_s1[row] = p1; g_s2[row] = p2; }
        }
    }
}

// -------------------------------------------------------- CSR build
__global__ void k_hist(const int* __restrict__ src) {
    int e = blockIdx.x * blockDim.x + threadIdx.x;
    if (e < EE) atomicAdd(&g_count[src[e]], 1);
}

__global__ void k_scan1() {
    __shared__ int warpsums[32];
    int i = blockIdx.x * 1024 + threadIdx.x;
    int lane = threadIdx.x & 31, w = threadIdx.x >> 5;
    int v = (i < NN) ? g_count[i] : 0;
    int sc = v;
#pragma unroll
    for (int off = 1; off < 32; off <<= 1) {
        int n = __shfl_up_sync(0xffffffffu, sc, off);
        if (lane >= off) sc += n;
    }
    if (lane == 31) warpsums[w] = sc;
    __syncthreads();
    if (w == 0) {
        int ws = warpsums[lane];
#pragma unroll
        for (int off = 1; off < 32; off <<= 1) {
            int n = __shfl_up_sync(0xffffffffu, ws, off);
            if (lane >= off) ws += n;
        }
        warpsums[lane] = ws;
    }
    __syncthreads();
    int base = (w > 0) ? warpsums[w - 1] : 0;
    int incl = sc + base;
    if (i < NN) g_rowstart[i] = incl - v;
    if (threadIdx.x == 1023) g_blocksum[blockIdx.x] = incl;
}

__global__ void k_scan2b() {
    __shared__ int s[64];
    int t = threadIdx.x;
    int v = (t < NB) ? g_blocksum[t] : 0;
    s[t] = v;
    __syncthreads();
#pragma unroll
    for (int off = 1; off < 64; off <<= 1) {
        int add = (t >= off) ? s[t - off] : 0;
        __syncthreads();
        s[t] += add;
        __syncthreads();
    }
    if (t < NB) g_blocksum[t] = s[t] - v;   // exclusive
}

__global__ void k_scan3() {
    int i = blockIdx.x * 1024 + threadIdx.x;
    if (i < NN) g_rowstart[i] += g_blocksum[blockIdx.x];
}

// permute + fused edge math: compute e = exp(-leaky_relu(s1[src]+s2[dst]))
// ONCE per edge here, store (dst, e) pair sorted by src.
__global__ void k_permute(const int* __restrict__ src, const int* __restrict__ dst) {
    int e = blockIdx.x * blockDim.x + threadIdx.x;
    if (e >= EE) return;
    int s = src[e], d = dst[e];
    float sc = g_s1[s] + g_s2[d];
    float lr = (sc >= 0.0f) ? sc : 0.2f * sc;
    float ev = expf(-lr);
    int pos = g_rowstart[s] + atomicAdd(&g_cur[s], 1);
    g_pair[pos] = make_int2(d, __float_as_int(ev));
}

// ------------------------------------------- gather + finalize (fused)
// One warp per node; no atomics, no transcendentals in the inner loop.
__global__ void k_gather(float* __restrict__ out) {
    int warp = blockIdx.x * 8 + (threadIdx.x >> 5);
    if (warp >= NN) return;
    int lane = threadIdx.x & 31;
    int start = g_rowstart[warp];
    int len = g_count[warp];

    float4 acc = make_float4(0.f, 0.f, 0.f, 0.f);
    float rowsum = 0.0f;

    int j = 0;
    for (; j + 1 < len; j += 2) {
        int2 p0 = g_pair[start + j];
        int2 p1 = g_pair[start + j + 1];
        float ev0 = __int_as_float(p0.y);
        float ev1 = __int_as_float(p1.y);
        float4 v0 = *(const float4*)(g_h + (size_t)p0.x * F + lane * 4);
        float4 v1 = *(const float4*)(g_h + (size_t)p1.x * F + lane * 4);
        rowsum += ev0 + ev1;
        acc.x += ev0 * v0.x + ev1 * v1.x;
        acc.y += ev0 * v0.y + ev1 * v1.y;
        acc.z += ev0 * v0.z + ev1 * v1.z;
        acc.w += ev0 * v0.w + ev1 * v1.w;
    }
    if (j < len) {
        int2 p0 = g_pair[start + j];
        float ev0 = __int_as_float(p0.y);
        float4 v0 = *(const float4*)(g_h + (size_t)p0.x * F + lane * 4);
        rowsum += ev0;
        acc.x += ev0 * v0.x; acc.y += ev0 * v0.y;
        acc.z += ev0 * v0.z; acc.w += ev0 * v0.w;
    }

    float inv = 1.0f / (rowsum + 1e-16f);
    float4 h4 = *(const float4*)(g_h + (size_t)warp * F + lane * 4);
    float4 r;
    float v;
    v = h4.x - acc.x * inv; r.x = (v > 0.f) ? v : expm1f(v);
    v = h4.y - acc.y * inv; r.y = (v > 0.f) ? v : expm1f(v);
    v = h4.z - acc.z * inv; r.z = (v > 0.f) ? v : expm1f(v);
    v = h4.w - acc.w * inv; r.w = (v > 0.f) ? v : expm1f(v);
    *(float4*)(out + (size_t)warp * F + lane * 4) = r;
}

// ---------------------------------------------------------------- launch
extern "C" void kernel_launch(void* const* d_in, const int* in_sizes, int n_in,
                              void* d_out, int out_size) {
    const float* x = (const float*)d_in[0];
    const float* W = (const float*)d_in[1];
    const float* a = (const float*)d_in[2];
    const int*   ei = (const int*)d_in[3];
    const int* src = ei;          // edge_index row 0
    const int* dst = ei + EE;     // edge_index row 1
    float* out = (float*)d_out;

    k_init   <<<(NN + 255) / 256, 256>>>();
    k_gemm   <<<(NN + 63) / 64,   256>>>(x, W, a);
    k_hist   <<<(EE + 255) / 256, 256>>>(src);
    k_scan1  <<<NB, 1024>>>();
    k_scan2b <<<1, 64>>>();
    k_scan3  <<<NB, 1024>>>();
    k_permute<<<(EE + 255) / 256, 256>>>(src, dst);
    k_gather <<<(NN + 7) / 8, 256>>>(out);
}

// round 7
// speedup vs baseline: 2.9324x; 1.0574x over previous
#include <cuda_runtime.h>
#include <math.h>

#define NN 50000
#define EE 640000
#define F  128
#define NB ((NN + 1023) / 1024)   // 49 scan blocks

// Scratch (static device globals: no allocation anywhere)
__device__ float g_h[NN * F];      // h = x @ W  (also mapped_fea)
__device__ float g_s1[NN];         // h[i] . a1
__device__ float g_s2[NN];         // h[i] . a2
__device__ int   g_count[NN];      // per-src edge count
__device__ int   g_rowstart[NN];   // exclusive prefix of count (global)
__device__ int   g_rank[EE];       // per-edge rank within its src segment
__device__ int   g_agg[64];        // per-scan-block aggregate (-1 = not ready)
__device__ int2  g_pair[EE];       // (dst, bitcast(e)) sorted by src

// packed f32x2 FMA: d.lo += a.lo*b.lo ; d.hi += a.hi*b.hi  (one fma-pipe slot)
#define FMA2(d, a, b) \
    asm("fma.rn.f32x2 %0, %1, %2, %0;" : "+l"(d) : "l"(a), "l"(b))

// ---------------------------------------------------------------- init
__global__ void k_init() {
    int i = blockIdx.x * blockDim.x + threadIdx.x;
    if (i < NN) g_count[i] = 0;
    if (i < 64) g_agg[i] = -1;
}

// ------------------- GEMM + s1/s2 epilogue + histogram tail (overlapped)
// Block: 256 threads (8 warps). Tile 64(M) x 128(N), K chunks of 32.
// Warp ty owns rows ty*8..ty*8+7 exclusively (x reads are pure broadcasts).
// Thread: 8 rows x 4 cols, accumulated as 8x2 packed f32x2.
__global__ void k_gemm(const float* __restrict__ x,
                       const float* __restrict__ W,
                       const float* __restrict__ a,
                       const int* __restrict__ src) {
    __shared__ __align__(16) float xs_dup[32][132];  // [k][2*row] duplicated x
    __shared__ __align__(16) float ws[32][128];

    const int tid = threadIdx.x;
    const int tx = tid & 31;         // lane
    const int ty = tid >> 5;         // warp = row group
    const int rowBase = blockIdx.x * 64;

    unsigned long long acc2[8][2];
#pragma unroll
    for (int i = 0; i < 8; i++) { acc2[i][0] = 0ULL; acc2[i][1] = 0ULL; }

    for (int k0 = 0; k0 < F; k0 += 32) {
        // x tile: 64 rows x 32 k -> dup-stored as (v,v) float2 pairs
#pragma unroll
        for (int p = 0; p < 2; p++) {
            int idx = p * 256 + tid;          // 512 float4 slots
            int r = idx >> 3;                 // 0..63
            int kg = idx & 7;                 // 0..7 (groups of 4 k)
            int row = rowBase + r;
            float4 v = make_float4(0.f, 0.f, 0.f, 0.f);
            if (row < NN) v = *(const float4*)&x[(size_t)row * F + k0 + kg * 4];
            *(float2*)&xs_dup[kg * 4 + 0][2 * r] = make_float2(v.x, v.x);
            *(float2*)&xs_dup[kg * 4 + 1][2 * r] = make_float2(v.y, v.y);
            *(float2*)&xs_dup[kg * 4 + 2][2 * r] = make_float2(v.z, v.z);
            *(float2*)&xs_dup[kg * 4 + 3][2 * r] = make_float2(v.w, v.w);
        }
        // W chunk: 32 k x 128 cols, natural layout (adjacent cols = f32x2 pair)
#pragma unroll
        for (int p = 0; p < 4; p++) {
            int idx = p * 256 + tid;          // 1024 float4 slots
            int k = idx >> 5, c4 = idx & 31;
            *(float4*)&ws[k][c4 * 4] = *(const float4*)&W[(size_t)(k0 + k) * F + c4 * 4];
        }
        __syncthreads();

#pragma unroll
        for (int kk = 0; kk < 32; kk++) {
            ulonglong2 wv = *(const ulonglong2*)&ws[kk][tx * 4];   // LDS.128
#pragma unroll
            for (int i = 0; i < 8; i++) {
                unsigned long long xv =                              // LDS.64 bcast
                    *(const unsigned long long*)&xs_dup[kk][2 * (ty * 8 + i)];
                FMA2(acc2[i][0], xv, wv.x);
                FMA2(acc2[i][1], xv, wv.y);
            }
        }
        __syncthreads();
    }

    // unpack accumulators
    float acc[8][4];
#pragma unroll
    for (int i = 0; i < 8; i++) {
        acc[i][0] = __uint_as_float((unsigned)(acc2[i][0] & 0xffffffffULL));
        acc[i][1] = __uint_as_float((unsigned)(acc2[i][0] >> 32));
        acc[i][2] = __uint_as_float((unsigned)(acc2[i][1] & 0xffffffffULL));
        acc[i][3] = __uint_as_float((unsigned)(acc2[i][1] >> 32));
    }

    // epilogue: write h; fused s1/s2 = h.a1, h.a2 via warp reduction
    float a1v[4], a2v[4];
#pragma unroll
    for (int j = 0; j < 4; j++) {
        a1v[j] = a[tx * 4 + j];
        a2v[j] = a[F + tx * 4 + j];
    }

#pragma unroll
    for (int i = 0; i < 8; i++) {
        int row = rowBase + ty * 8 + i;
        float p1 = acc[i][0] * a1v[0] + acc[i][1] * a1v[1] +
                   acc[i][2] * a1v[2] + acc[i][3] * a1v[3];
        float p2 = acc[i][0] * a2v[0] + acc[i][1] * a2v[1] +
                   acc[i][2] * a2v[2] + acc[i][3] * a2v[3];
#pragma unroll
        for (int off = 16; off > 0; off >>= 1) {
            p1 += __shfl_xor_sync(0xffffffffu, p1, off);
            p2 += __shfl_xor_sync(0xffffffffu, p2, off);
        }
        if (row < NN) {
            float4 o;
            o.x = acc[i][0]; o.y = acc[i][1]; o.z = acc[i][2]; o.w = acc[i][3];
            *(float4*)&g_h[row * F + tx * 4] = o;
            if (tx == 0) { g_s1[row] = p1; g_s2[row] = p2; }
        }
    }

    // ---- histogram tail: independent of GEMM math, overlaps with other
    // blocks still in their fma mainloop. Also yields per-edge rank.
    int stride = gridDim.x * blockDim.x;
    for (int e = blockIdx.x * blockDim.x + tid; e < EE; e += stride) {
        int s = src[e];
        g_rank[e] = atomicAdd(&g_count[s], 1);
    }
}

// ---------------- single-kernel exclusive scan (decoupled aggregates)
// 49 blocks <= 148 SMs -> all co-resident, so polling is deadlock-free.
__global__ void k_scan() {
    __shared__ int warpsums[32];
    __shared__ int s_prev;
    const int b = blockIdx.x;
    const int i = b * 1024 + threadIdx.x;
    const int lane = threadIdx.x & 31, w = threadIdx.x >> 5;

    int v = (i < NN) ? g_count[i] : 0;
    int sc = v;
#pragma unroll
    for (int off = 1; off < 32; off <<= 1) {
        int n = __shfl_up_sync(0xffffffffu, sc, off);
        if (lane >= off) sc += n;
    }
    if (lane == 31) warpsums[w] = sc;
    if (threadIdx.x == 0) s_prev = 0;
    __syncthreads();
    if (w == 0) {
        int ws = warpsums[lane];
#pragma unroll
        for (int off = 1; off < 32; off <<= 1) {
            int n = __shfl_up_sync(0xffffffffu, ws, off);
            if (lane >= off) ws += n;
        }
        warpsums[lane] = ws;
    }
    __syncthreads();

    // publish this block's aggregate (value IS the ready flag; -1 = not ready)
    if (threadIdx.x == 0) atomicExch(&g_agg[b], warpsums[31]);

    // sum all predecessors' aggregates (parallel poll, one lane per block)
    if (threadIdx.x < b) {
        volatile int* p = &g_agg[threadIdx.x];
        int a;
        do { a = *p; } while (a < 0);
        atomicAdd(&s_prev, a);
    }
    __syncthreads();

    int base = (w > 0) ? warpsums[w - 1] : 0;
    if (i < NN) g_rowstart[i] = (sc + base - v) + s_prev;
}

// ----------------- permute (atomic-free) + fused edge weight e = exp(-lrelu)
__global__ void k_permute(const int* __restrict__ src, const int* __restrict__ dst) {
    int e = blockIdx.x * blockDim.x + threadIdx.x;
    if (e >= EE) return;
    int s = src[e], d = dst[e];
    float sc = g_s1[s] + g_s2[d];
    float lr = (sc >= 0.0f) ? sc : 0.2f * sc;
    float ev = expf(-lr);
    int pos = g_rowstart[s] + g_rank[e];
    g_pair[pos] = make_int2(d, __float_as_int(ev));
}

// ------------------------------------------- gather + finalize (fused)
// One warp per node; no atomics, no transcendentals in the inner loop.
__global__ void k_gather(float* __restrict__ out) {
    int warp = blockIdx.x * 8 + (threadIdx.x >> 5);
    if (warp >= NN) return;
    int lane = threadIdx.x & 31;
    int start = g_rowstart[warp];
    int len = g_count[warp];

    float4 acc = make_float4(0.f, 0.f, 0.f, 0.f);
    float rowsum = 0.0f;

    int j = 0;
    for (; j + 1 < len; j += 2) {
        int2 p0 = g_pair[start + j];
        int2 p1 = g_pair[start + j + 1];
        float ev0 = __int_as_float(p0.y);
        float ev1 = __int_as_float(p1.y);
        float4 v0 = *(const float4*)(g_h + (size_t)p0.x * F + lane * 4);
        float4 v1 = *(const float4*)(g_h + (size_t)p1.x * F + lane * 4);
        rowsum += ev0 + ev1;
        acc.x += ev0 * v0.x + ev1 * v1.x;
        acc.y += ev0 * v0.y + ev1 * v1.y;
        acc.z += ev0 * v0.z + ev1 * v1.z;
        acc.w += ev0 * v0.w + ev1 * v1.w;
    }
    if (j < len) {
        int2 p0 = g_pair[start + j];
        float ev0 = __int_as_float(p0.y);
        float4 v0 = *(const float4*)(g_h + (size_t)p0.x * F + lane * 4);
        rowsum += ev0;
        acc.x += ev0 * v0.x; acc.y += ev0 * v0.y;
        acc.z += ev0 * v0.z; acc.w += ev0 * v0.w;
    }

    float inv = 1.0f / (rowsum + 1e-16f);
    float4 h4 = *(const float4*)(g_h + (size_t)warp * F + lane * 4);
    float4 r;
    float v;
    v = h4.x - acc.x * inv; r.x = (v > 0.f) ? v : expm1f(v);
    v = h4.y - acc.y * inv; r.y = (v > 0.f) ? v : expm1f(v);
    v = h4.z - acc.z * inv; r.z = (v > 0.f) ? v : expm1f(v);
    v = h4.w - acc.w * inv; r.w = (v > 0.f) ? v : expm1f(v);
    *(float4*)(out + (size_t)warp * F + lane * 4) = r;
}

// ---------------------------------------------------------------- launch
extern "C" void kernel_launch(void* const* d_in, const int* in_sizes, int n_in,
                              void* d_out, int out_size) {
    const float* x = (const float*)d_in[0];
    const float* W = (const float*)d_in[1];
    const float* a = (const float*)d_in[2];
    const int*   ei = (const int*)d_in[3];
    const int* src = ei;          // edge_index row 0
    const int* dst = ei + EE;     // edge_index row 1
    float* out = (float*)d_out;

    k_init   <<<(NN + 255) / 256, 256>>>();
    k_gemm   <<<(NN + 63) / 64,   256>>>(x, W, a, src);
    k_scan   <<<NB, 1024>>>();
    k_permute<<<(EE + 255) / 256, 256>>>(src, dst);
    k_gather <<<(NN + 7) / 8, 256>>>(out);
}

// round 9
// speedup vs baseline: 3.6454x; 1.2431x over previous
#include <cuda_runtime.h>
#include <cuda_bf16.h>
#include <math.h>

#define NN 50000
#define EE 640000
#define F  128
#define NB ((NN + 1023) / 1024)          // 49 scan blocks
#define GB ((NN + 127) / 128)            // 391 gemm blocks

// ---- smem layout (bytes). Rows padded to 272B (136 bf16) -> ldmatrix conflict-free
#define ROWB 272
#define AH_OFF 0
#define AL_OFF 34816
#define BH_OFF 69632
#define BL_OFF 104448
#define S1_OFF 139264
#define S2_OFF 139776
#define SMEM_BYTES 140288

// Scratch (static device globals: no allocation anywhere)
__device__ float g_h[NN * F];
__device__ float g_s1[NN];
__device__ float g_s2[NN];
__device__ int   g_count[NN];
__device__ int   g_rowstart[NN];
__device__ int   g_rank[EE];
__device__ int   g_agg[64];
__device__ int2  g_pair[EE];
__device__ unsigned g_Bimg[16384];   // [BH: 8192 u32][BL: 8192 u32], [n][k] bf16 pairs

// ------------------------------------------------ PTX helpers (baseline ISA only)
__device__ __forceinline__ unsigned smem_u32(const void* p) {
    unsigned a;
    asm("{ .reg .u64 t; cvta.to.shared.u64 t, %1; cvt.u32.u64 %0, t; }"
        : "=r"(a) : "l"(p));
    return a;
}
__device__ __forceinline__ void ldm4(unsigned r[4], unsigned addr) {
    asm volatile("ldmatrix.sync.aligned.m8n8.x4.shared.b16 {%0,%1,%2,%3}, [%4];"
                 : "=r"(r[0]), "=r"(r[1]), "=r"(r[2]), "=r"(r[3]) : "r"(addr));
}
__device__ __forceinline__ void mma16816(float c[4], const unsigned a[4],
                                         unsigned b0, unsigned b1) {
    asm volatile("mma.sync.aligned.m16n8k16.row.col.f32.bf16.bf16.f32 "
                 "{%0,%1,%2,%3}, {%4,%5,%6,%7}, {%8,%9}, {%0,%1,%2,%3};"
                 : "+f"(c[0]), "+f"(c[1]), "+f"(c[2]), "+f"(c[3])
                 : "r"(a[0]), "r"(a[1]), "r"(a[2]), "r"(a[3]), "r"(b0), "r"(b1));
}
__device__ __forceinline__ unsigned pack_bf16(float x, float y) {
    unsigned short hx = __bfloat16_as_ushort(__float2bfloat16(x));
    unsigned short hy = __bfloat16_as_ushort(__float2bfloat16(y));
    return (unsigned)hx | ((unsigned)hy << 16);
}
__device__ __forceinline__ float bf16hi_f(float x) {   // value of bf16(x)
    unsigned short h = __bfloat16_as_ushort(__float2bfloat16(x));
    return __uint_as_float(((unsigned)h) << 16);
}

// -------------------- prep: init counters + W -> bf16 hi/lo images [n][k]
__global__ void k_prep(const float* __restrict__ W) {
    int t = blockIdx.x * blockDim.x + threadIdx.x;
    if (t < NN) g_count[t] = 0;
    if (t < 64) g_agg[t] = -1;
    if (t < 8192) {
        int n = t >> 6, q = t & 63, k = 2 * q;
        float v0 = W[(size_t)k * F + n];          // B[n][k] = W[k][n]
        float v1 = W[(size_t)(k + 1) * F + n];
        float h0 = bf16hi_f(v0), h1 = bf16hi_f(v1);
        g_Bimg[n * 64 + q]        = pack_bf16(v0, v1);
        g_Bimg[8192 + n * 64 + q] = pack_bf16(v0 - h0, v1 - h1);
    }
}

// ------------- GEMM via mma.sync bf16-split + s1/s2 epilogue + hist tail
__global__ void __launch_bounds__(256, 1)
k_gemm(const float* __restrict__ x, const float* __restrict__ a,
       const int* __restrict__ src) {
    extern __shared__ char dsm[];
    const unsigned base = smem_u32(dsm);
    float* s_s1 = (float*)(dsm + S1_OFF);
    float* s_s2 = (float*)(dsm + S2_OFF);

    const int tid = threadIdx.x;
    const int lane = tid & 31;
    const int wid = tid >> 5;
    const int warp_m = wid >> 1;          // 0..3 -> rows warp_m*32..+31
    const int warp_n = wid & 1;           // 0..1 -> cols warp_n*64..+63
    const int rowBase = blockIdx.x * 128;

    // ---- phase 1: fill smem ----
    // B images -> padded smem rows
    const float4* bimg4 = (const float4*)g_Bimg;
#pragma unroll
    for (int p = 0; p < 16; p++) {
        int i = p * 256 + tid;            // 4096 float4 (BH 2048 + BL 2048)
        int half = i >> 11, j = i & 2047;
        int n = j >> 4, f4 = j & 15;
        *(float4*)(dsm + (half ? BL_OFF : BH_OFF) + n * ROWB + f4 * 16) = bimg4[i];
    }
    // x tile -> bf16 hi/lo split, padded rows
#pragma unroll
    for (int p = 0; p < 16; p++) {
        int idx = p * 256 + tid;          // 4096 float4 slots (128 rows x 32)
        int row = idx >> 5;
        int col0 = (idx & 31) * 4;
        int grow = rowBase + row;
        float4 v = make_float4(0.f, 0.f, 0.f, 0.f);
        if (grow < NN) v = *(const float4*)&x[(size_t)grow * F + col0];
        unsigned h01 = pack_bf16(v.x, v.y);
        unsigned h23 = pack_bf16(v.z, v.w);
        unsigned l01 = pack_bf16(v.x - bf16hi_f(v.x), v.y - bf16hi_f(v.y));
        unsigned l23 = pack_bf16(v.z - bf16hi_f(v.z), v.w - bf16hi_f(v.w));
        unsigned o = row * ROWB + col0 * 2;
        asm volatile("st.shared.v2.b32 [%0], {%1, %2};"
                     :: "r"(base + AH_OFF + o), "r"(h01), "r"(h23));
        asm volatile("st.shared.v2.b32 [%0], {%1, %2};"
                     :: "r"(base + AL_OFF + o), "r"(l01), "r"(l23));
    }
    if (tid < 128) { s_s1[tid] = 0.f; s_s2[tid] = 0.f; }
    __syncthreads();

    // ---- phase 2: mainloop ----
    float acc[2][8][4];
#pragma unroll
    for (int mi = 0; mi < 2; mi++)
#pragma unroll
        for (int ni = 0; ni < 8; ni++)
#pragma unroll
            for (int q = 0; q < 4; q++) acc[mi][ni][q] = 0.f;

    // ldmatrix lane->tile-row mapping
    const int lrA = (lane & 7) + ((lane >> 3) & 1) * 8;   // A: tiles (m0-7,m8-15,k+8 dup)
    const int kbA = (lane >> 4) * 16;
    const int lrB = (lane & 7) + (lane >> 4) * 8;          // B: tiles (n0-7@k0, n0-7@k8, n8-15...)
    const int kbB = ((lane >> 3) & 1) * 16;

    const unsigned aRowA = base + (warp_m * 32 + lrA) * ROWB + kbA;
    const unsigned aRowB = base + (warp_n * 64 + lrB) * ROWB + kbB;

    for (int k = 0; k < 8; k++) {
        const int kb = k * 32;            // k0*2 bytes
        unsigned ah[2][4], al[2][4], bh[4][4], bl[4][4];
#pragma unroll
        for (int mi = 0; mi < 2; mi++) {
            ldm4(ah[mi], aRowA + AH_OFF + mi * 16 * ROWB + kb);
            ldm4(al[mi], aRowA + AL_OFF + mi * 16 * ROWB + kb);
        }
#pragma unroll
        for (int j = 0; j < 4; j++) {
            ldm4(bh[j], aRowB + BH_OFF + j * 16 * ROWB + kb);
            ldm4(bl[j], aRowB + BL_OFF + j * 16 * ROWB + kb);
        }
#pragma unroll
        for (int mi = 0; mi < 2; mi++)
#pragma unroll
            for (int j = 0; j < 4; j++) {
                mma16816(acc[mi][2 * j],     ah[mi], bh[j][0], bh[j][1]);
                mma16816(acc[mi][2 * j + 1], ah[mi], bh[j][2], bh[j][3]);
                mma16816(acc[mi][2 * j],     ah[mi], bl[j][0], bl[j][1]);
                mma16816(acc[mi][2 * j + 1], ah[mi], bl[j][2], bl[j][3]);
                mma16816(acc[mi][2 * j],     al[mi], bh[j][0], bh[j][1]);
                mma16816(acc[mi][2 * j + 1], al[mi], bh[j][2], bh[j][3]);
            }
    }

    // ---- phase 3: epilogue — write h, fused s1/s2 partials ----
    float p1[2][2] = {{0.f, 0.f}, {0.f, 0.f}};
    float p2[2][2] = {{0.f, 0.f}, {0.f, 0.f}};
#pragma unroll
    for (int ni = 0; ni < 8; ni++) {
        int c = warp_n * 64 + ni * 8 + 2 * (lane & 3);
        float A1x = a[c], A1y = a[c + 1];
        float A2x = a[F + c], A2y = a[F + c + 1];
#pragma unroll
        for (int mi = 0; mi < 2; mi++) {
            float* f = acc[mi][ni];
            p1[mi][0] += f[0] * A1x + f[1] * A1y;
            p2[mi][0] += f[0] * A2x + f[1] * A2y;
            p1[mi][1] += f[2] * A1x + f[3] * A1y;
            p2[mi][1] += f[2] * A2x + f[3] * A2y;
            int row0 = rowBase + warp_m * 32 + mi * 16 + (lane >> 2);
            if (row0 < NN)
                *(float2*)&g_h[(size_t)row0 * F + c] = make_float2(f[0], f[1]);
            if (row0 + 8 < NN)
                *(float2*)&g_h[(size_t)(row0 + 8) * F + c] = make_float2(f[2], f[3]);
        }
    }
    // quad-reduce (lanes sharing a row differ in lane&3)
#pragma unroll
    for (int mi = 0; mi < 2; mi++)
#pragma unroll
        for (int hf = 0; hf < 2; hf++) {
            float v1 = p1[mi][hf], v2 = p2[mi][hf];
            v1 += __shfl_xor_sync(0xffffffffu, v1, 1);
            v1 += __shfl_xor_sync(0xffffffffu, v1, 2);
            v2 += __shfl_xor_sync(0xffffffffu, v2, 1);
            v2 += __shfl_xor_sync(0xffffffffu, v2, 2);
            if ((lane & 3) == 0) {
                int lr = warp_m * 32 + mi * 16 + hf * 8 + (lane >> 2);
                atomicAdd(&s_s1[lr], v1);
                atomicAdd(&s_s2[lr], v2);
            }
        }
    __syncthreads();
    if (tid < 128) {
        int row = rowBase + tid;
        if (row < NN) { g_s1[row] = s_s1[tid]; g_s2[row] = s_s2[tid]; }
    }

    // ---- phase 4: histogram tail (independent work) ----
    for (int e = blockIdx.x * 256 + tid; e < EE; e += GB * 256)
        g_rank[e] = atomicAdd(&g_count[src[e]], 1);
}

// ---------------- single-kernel exclusive scan (decoupled aggregates)
__global__ void k_scan() {
    __shared__ int warpsums[32];
    __shared__ int s_prev;
    const int b = blockIdx.x;
    const int i = b * 1024 + threadIdx.x;
    const int lane = threadIdx.x & 31, w = threadIdx.x >> 5;

    int v = (i < NN) ? g_count[i] : 0;
    int sc = v;
#pragma unroll
    for (int off = 1; off < 32; off <<= 1) {
        int n = __shfl_up_sync(0xffffffffu, sc, off);
        if (lane >= off) sc += n;
    }
    if (lane == 31) warpsums[w] = sc;
    if (threadIdx.x == 0) s_prev = 0;
    __syncthreads();
    if (w == 0) {
        int ws = warpsums[lane];
#pragma unroll
        for (int off = 1; off < 32; off <<= 1) {
            int n = __shfl_up_sync(0xffffffffu, ws, off);
            if (lane >= off) ws += n;
        }
        warpsums[lane] = ws;
    }
    __syncthreads();

    if (threadIdx.x == 0) atomicExch(&g_agg[b], warpsums[31]);
    if (threadIdx.x < b) {
        volatile int* p = &g_agg[threadIdx.x];
        int ag;
        do { ag = *p; } while (ag < 0);
        atomicAdd(&s_prev, ag);
    }
    __syncthreads();

    int basew = (w > 0) ? warpsums[w - 1] : 0;
    if (i < NN) g_rowstart[i] = (sc + basew - v) + s_prev;
}

// ----------------- permute (atomic-free) + fused edge weight
__global__ void k_permute(const int* __restrict__ src, const int* __restrict__ dst) {
    int e = blockIdx.x * blockDim.x + threadIdx.x;
    if (e >= EE) return;
    int s = src[e], d = dst[e];
    float sc = g_s1[s] + g_s2[d];
    float lr = (sc >= 0.0f) ? sc : 0.2f * sc;
    float ev = expf(-lr);
    int pos = g_rowstart[s] + g_rank[e];
    g_pair[pos] = make_int2(d, __float_as_int(ev));
}

// ------------------------------------------- gather + finalize (fused)
__global__ void k_gather(float* __restrict__ out) {
    int warp = blockIdx.x * 8 + (threadIdx.x >> 5);
    if (warp >= NN) return;
    int lane = threadIdx.x & 31;
    int start = g_rowstart[warp];
    int len = g_count[warp];

    float4 acc = make_float4(0.f, 0.f, 0.f, 0.f);
    float rowsum = 0.0f;

    int j = 0;
    for (; j + 1 < len; j += 2) {
        int2 p0 = g_pair[start + j];
        int2 p1 = g_pair[start + j + 1];
        float ev0 = __int_as_float(p0.y);
        float ev1 = __int_as_float(p1.y);
        float4 v0 = *(const float4*)(g_h + (size_t)p0.x * F + lane * 4);
        float4 v1 = *(const float4*)(g_h + (size_t)p1.x * F + lane * 4);
        rowsum += ev0 + ev1;
        acc.x += ev0 * v0.x + ev1 * v1.x;
        acc.y += ev0 * v0.y + ev1 * v1.y;
        acc.z += ev0 * v0.z + ev1 * v1.z;
        acc.w += ev0 * v0.w + ev1 * v1.w;
    }
    if (j < len) {
        int2 p0 = g_pair[start + j];
        float ev0 = __int_as_float(p0.y);
        float4 v0 = *(const float4*)(g_h + (size_t)p0.x * F + lane * 4);
        rowsum += ev0;
        acc.x += ev0 * v0.x; acc.y += ev0 * v0.y;
        acc.z += ev0 * v0.z; acc.w += ev0 * v0.w;
    }

    float inv = 1.0f / (rowsum + 1e-16f);
    float4 h4 = *(const float4*)(g_h + (size_t)warp * F + lane * 4);
    float4 r;
    float v;
    v = h4.x - acc.x * inv; r.x = (v > 0.f) ? v : expm1f(v);
    v = h4.y - acc.y * inv; r.y = (v > 0.f) ? v : expm1f(v);
    v = h4.z - acc.z * inv; r.z = (v > 0.f) ? v : expm1f(v);
    v = h4.w - acc.w * inv; r.w = (v > 0.f) ? v : expm1f(v);
    *(float4*)(out + (size_t)warp * F + lane * 4) = r;
}

// ---------------------------------------------------------------- launch
extern "C" void kernel_launch(void* const* d_in, const int* in_sizes, int n_in,
                              void* d_out, int out_size) {
    const float* x = (const float*)d_in[0];
    const float* W = (const float*)d_in[1];
    const float* a = (const float*)d_in[2];
    const int*   ei = (const int*)d_in[3];
    const int* src = ei;
    const int* dst = ei + EE;
    float* out = (float*)d_out;

    cudaFuncSetAttribute(k_gemm, cudaFuncAttributeMaxDynamicSharedMemorySize,
                         SMEM_BYTES);

    k_prep   <<<(NN + 255) / 256, 256>>>(W);
    k_gemm   <<<GB, 256, SMEM_BYTES>>>(x, a, src);
    k_scan   <<<NB, 1024>>>();
    k_permute<<<(EE + 255) / 256, 256>>>(src, dst);
    k_gather <<<(NN + 7) / 8, 256>>>(out);
}